// round 6
// baseline (speedup 1.0000x reference)
#include <cuda_runtime.h>
#include <math.h>

// Shapes fixed by the reference:
//   pred:              [N, 6]
//   dropout_preds:     [K, M, 6]
//   dropout_cls_confs: [K, M, C]
//   out:               [N]
#define N_PRED 1000
#define M_BOX  2000
#define M_PAD  2048          // padded with never-hit boxes -> no bounds checks
#define K_PASS 10
#define C_CLS  80
#define EPS_F  1e-7f

// Repacked boxes: aligned float4 (x1,y1,x2,y2); pads are all-zero boxes,
// which can never satisfy the hit test (intersection = 0 < s1 > 0).
__device__ float4 g_box[K_PASS * M_PAD];

__global__ void prep_kernel(const float* __restrict__ dp)
{
    const int i = blockIdx.x * blockDim.x + threadIdx.x;
    if (i < K_PASS * M_PAD) {
        const int kk = i >> 11;        // / 2048
        const int mm = i & (M_PAD - 1);
        float4 v = make_float4(0.f, 0.f, 0.f, 0.f);
        if (mm < M_BOX) {
            const float* b = dp + ((size_t)kk * M_BOX + mm) * 6;
            v = make_float4(b[0], b[1], b[2], b[3]);
        }
        g_box[i] = v;
    }
}

// IoU > 0.5  <=>  3*inter > (area1+eps) + area2  <=>  fma(3,inter,-area2) > s1
// (denominator of IoU strictly positive)
__device__ __forceinline__ bool iou_hit(float4 v,
                                        float px1, float py1, float px2, float py2,
                                        float s1)
{
    const float w = fminf(px2, v.z) - fmaxf(px1, v.x);
    const float h = fminf(py2, v.w) - fmaxf(py1, v.y);
    const float inter = fmaxf(w, 0.0f) * fmaxf(h, 0.0f);
    const float area2 = (v.z - v.x) * (v.w - v.y);
    return fmaf(3.0f, inter, -area2) > s1;
}

// One block per pred n (reversed: heavy scans first); one warp per pass k.
//
// Key idea: first-match == min hit index over any PREFIX that contains a hit.
// The jittered copy at m = n guarantees a hit at m <= n (virtually always), so
// scan [0, round_up(n+1,128)) with a FLAT, dependency-free loop (no per-chunk
// ballot/branch) and take one REDUX.MIN at the end. Rare fallback: chunked
// early-exit scan over the remainder.
__global__ __launch_bounds__(K_PASS * 32)
void ue_cls_kernel(const float* __restrict__ pred,
                   const float* __restrict__ conf,
                   float* __restrict__ out)
{
    const int n    = (N_PRED - 1) - blockIdx.x;   // heavy blocks first
    const int k    = threadIdx.x >> 5;
    const int lane = threadIdx.x & 31;

    __shared__ float s_u[K_PASS];
    __shared__ int   s_m[K_PASS];

    const float px1 = pred[n * 6 + 0];
    const float py1 = pred[n * 6 + 1];
    const float px2 = pred[n * 6 + 2];
    const float py2 = pred[n * 6 + 3];
    const float s1  = (px2 - px1) * (py2 - py1) + EPS_F;

    const float4* __restrict__ bp = g_box + k * M_PAD + lane;

    const int X = (n + 128) & ~127;   // round_up(n+1, 128), <= 1024

    int loc = 0x7fffffff;

    // Flat prefix scan: all iterations independent -> full pipelining / MLP.
    #pragma unroll 2
    for (int base = 0; base < X; base += 128) {
        const float4 v0 = bp[base];
        const float4 v1 = bp[base + 32];
        const float4 v2 = bp[base + 64];
        const float4 v3 = bp[base + 96];
        if (iou_hit(v0, px1, py1, px2, py2, s1)) loc = min(loc, base + lane);
        if (iou_hit(v1, px1, py1, px2, py2, s1)) loc = min(loc, base + 32 + lane);
        if (iou_hit(v2, px1, py1, px2, py2, s1)) loc = min(loc, base + 64 + lane);
        if (iou_hit(v3, px1, py1, px2, py2, s1)) loc = min(loc, base + 96 + lane);
    }

    int m_match = __reduce_min_sync(0xffffffffu, loc);

    if (m_match == 0x7fffffff) {
        // Rare: no hit in [0, X). Chunked early-exit scan of the remainder.
        m_match = -1;
        for (int base = X; base < M_PAD; base += 128) {
            const float4 v0 = bp[base];
            const float4 v1 = bp[base + 32];
            const float4 v2 = bp[base + 64];
            const float4 v3 = bp[base + 96];
            int l2 = 0x7fffffff;
            if (iou_hit(v3, px1, py1, px2, py2, s1)) l2 = 96 + lane;
            if (iou_hit(v2, px1, py1, px2, py2, s1)) l2 = 64 + lane;
            if (iou_hit(v1, px1, py1, px2, py2, s1)) l2 = 32 + lane;
            if (iou_hit(v0, px1, py1, px2, py2, s1)) l2 = lane;
            const int r = __reduce_min_sync(0xffffffffu, l2);
            if (r != 0x7fffffff) { m_match = base + r; break; }
        }
    }

    if (lane == 0) s_m[k] = m_match;

    if (m_match >= 0) {
        // Cooperative entropy of the matched row: C=80 = 32 + 32 + 16.
        const float* __restrict__ row =
            conf + ((size_t)k * M_BOX + (size_t)m_match) * C_CLS;
        float s;
        {
            const float p0 = row[lane];
            const float p1 = row[lane + 32];
            s = p0 * __logf(p0) + p1 * __logf(p1);
        }
        if (lane < C_CLS - 64) {
            const float p2 = row[lane + 64];
            s += p2 * __logf(p2);
        }
        #pragma unroll
        for (int off = 16; off; off >>= 1)
            s += __shfl_xor_sync(0xffffffffu, s, off);
        // u = 1 - entropy/log(C) = 1 + s/log(C)
        if (lane == 0) s_u[k] = 1.0f + s * (1.0f / logf((float)C_CLS));
    }

    __syncthreads();

    if (threadIdx.x == 0) {
        float sum = 0.0f;
        int   cnt = 0;
        #pragma unroll
        for (int kk = 0; kk < K_PASS; kk++) {
            if (s_m[kk] >= 0) { sum += s_u[kk]; cnt++; }
        }
        out[n] = (cnt > 0) ? (sum / (float)cnt) : __int_as_float(0x7fc00000);
    }
}

extern "C" void kernel_launch(void* const* d_in, const int* in_sizes, int n_in,
                              void* d_out, int out_size)
{
    const float* pred = (const float*)d_in[0];
    const float* dp   = (const float*)d_in[1];
    const float* conf = (const float*)d_in[2];
    float* out = (float*)d_out;

    prep_kernel<<<(K_PASS * M_PAD + 255) / 256, 256>>>(dp);
    ue_cls_kernel<<<N_PRED, K_PASS * 32>>>(pred, conf, out);
}

// round 7
// speedup vs baseline: 1.0742x; 1.0742x over previous
#include <cuda_runtime.h>
#include <math.h>

// Shapes fixed by the reference:
//   pred:              [N, 6]
//   dropout_preds:     [K, M, 6]
//   dropout_cls_confs: [K, M, C]
//   out:               [N]
#define N_PRED 1000
#define M_BOX  2000
#define M_PAD  2048          // padded with never-hit zero boxes
#define K_PASS 10
#define C_CLS  80
#define EPS_F  1e-7f
#define CAP    64            // candidate list capacity (overflow -> exact fallback)
#define INF_I  0x7fffffff

// Repacked boxes (float4, aligned); pads are zero boxes (can never hit: the
// pred box always has px2 > 0, so intersection with (0,0,0,0) is empty).
__device__ float4   g_box[K_PASS * M_PAD];
__device__ float4   g_pred4[N_PRED];
__device__ unsigned g_dev = 0;   // float bits of max |box - pred| over copies

__global__ void prep_kernel(const float* __restrict__ pred,
                            const float* __restrict__ dp)
{
    const int i = blockIdx.x * blockDim.x + threadIdx.x;
    float dev = 0.0f;

    if (i < K_PASS * M_PAD) {
        const int kk = i >> 11;          // / 2048
        const int mm = i & (M_PAD - 1);
        float4 v = make_float4(0.f, 0.f, 0.f, 0.f);
        if (mm < M_BOX) {
            const float* b = dp + ((size_t)kk * M_BOX + mm) * 6;
            v = make_float4(b[0], b[1], b[2], b[3]);
        }
        g_box[i] = v;
        if (mm < N_PRED) {
            // deviation of this jittered copy from its source pred
            const float* p = pred + (size_t)mm * 6;
            dev = fmaxf(fmaxf(fabsf(v.x - p[0]), fabsf(v.y - p[1])),
                        fmaxf(fabsf(v.z - p[2]), fabsf(v.w - p[3])));
        }
    }
    if (i < N_PRED) {
        const float* p = pred + (size_t)i * 6;
        g_pred4[i] = make_float4(p[0], p[1], p[2], p[3]);
    }

    // block-reduce max dev, one atomicMax per block (positive floats order as uints)
    __shared__ unsigned s_w[8];
    const unsigned bits = __float_as_uint(dev);
    const unsigned wmax = __reduce_max_sync(0xffffffffu, bits);
    if ((threadIdx.x & 31) == 0) s_w[threadIdx.x >> 5] = wmax;
    __syncthreads();
    if (threadIdx.x == 0) {
        unsigned m = 0;
        #pragma unroll
        for (int w = 0; w < 8; w++) m = max(m, s_w[w]);
        atomicMax(&g_dev, m);
    }
}

// Exact hit: IoU > 0.5  <=>  3*inter > (area1+eps) + area2, s1 = area1+eps.
__device__ __forceinline__ bool iou_hit(float4 v,
                                        float px1, float py1, float px2, float py2,
                                        float s1)
{
    const float w = fminf(px2, v.z) - fmaxf(px1, v.x);
    const float h = fminf(py2, v.w) - fmaxf(py1, v.y);
    const float inter = fmaxf(w, 0.0f) * fmaxf(h, 0.0f);
    const float area2 = (v.z - v.x) * (v.w - v.y);
    return fmaf(3.0f, inter, -area2) > s1;
}

// One block per pred n; one warp per pass k.
// Phase 1: screen all preds with a SOUND IoU upper bound (jitter <= D):
//   expand B by D for intersection UB, shrink by 2D for area LB. Any actual
//   hit among copies must pass this test -> candidate superset is exact.
// Phase 2: exact test of candidates only; min hit index == first match.
__global__ __launch_bounds__(K_PASS * 32)
void ue_cls_kernel(const float* __restrict__ conf,
                   float* __restrict__ out)
{
    const int n    = blockIdx.x;
    const int tid  = threadIdx.x;
    const int k    = tid >> 5;
    const int lane = tid & 31;

    __shared__ int   s_cand[CAP];
    __shared__ int   s_cnt;
    __shared__ float s_u[K_PASS];
    __shared__ int   s_m[K_PASS];

    const float4 A  = g_pred4[n];
    const float  a1 = (A.z - A.x) * (A.w - A.y);
    const float  s1 = a1 + EPS_F;
    // inflate D: covers fp rounding of the bound with huge margin
    const float  Dv = __uint_as_float(g_dev) * 1.01f + 0.5f;

    if (tid == 0) s_cnt = 0;
    __syncthreads();

    // ---- Phase 1: sound candidate screen over all preds (~3 per thread) ----
    for (int n2 = tid; n2 < N_PRED; n2 += K_PASS * 32) {
        const float4 B = g_pred4[n2];
        const float w_ub = fminf(A.z, B.z + Dv) - fmaxf(A.x, B.x - Dv);
        const float h_ub = fminf(A.w, B.w + Dv) - fmaxf(A.y, B.y - Dv);
        const float inter_ub = fmaxf(w_ub, 0.0f) * fmaxf(h_ub, 0.0f);
        const float a2_lb = fmaxf(B.z - B.x - 2.0f * Dv, 0.0f) *
                            fmaxf(B.w - B.y - 2.0f * Dv, 0.0f);
        if (3.0f * inter_ub > a1 + a2_lb) {          // bound > 0.5 (eps dropped: looser)
            const int pos = atomicAdd(&s_cnt, 1);
            if (pos < CAP) s_cand[pos] = n2;
        }
    }
    __syncthreads();
    const int cnt = s_cnt;

    const float4* __restrict__ bp = g_box + k * M_PAD;

    int m_match = -1;

    if (cnt <= CAP) {
        // ---- Phase 2: exact test of candidates (copies region, m < 1000) ----
        int loc = INF_I;
        for (int c = lane; c < cnt; c += 32) {
            const int m = s_cand[c];
            if (iou_hit(bp[m], A.x, A.y, A.z, A.w, s1)) loc = min(loc, m);
        }
        m_match = __reduce_min_sync(0xffffffffu, loc);

        if (m_match == INF_I) {
            // Rare: no copy hit. First match (if any) is in the random region
            // [1000, 2000): chunked early-exit scan (pads never hit).
            m_match = -1;
            for (int base = N_PRED; base < 2024; base += 128) {
                const float4 v0 = bp[base + lane];
                const float4 v1 = bp[base + 32 + lane];
                const float4 v2 = bp[base + 64 + lane];
                const float4 v3 = bp[base + 96 + lane];
                int l2 = INF_I;
                if (iou_hit(v3, A.x, A.y, A.z, A.w, s1)) l2 = 96 + lane;
                if (iou_hit(v2, A.x, A.y, A.z, A.w, s1)) l2 = 64 + lane;
                if (iou_hit(v1, A.x, A.y, A.z, A.w, s1)) l2 = 32 + lane;
                if (iou_hit(v0, A.x, A.y, A.z, A.w, s1)) l2 = lane;
                const int r = __reduce_min_sync(0xffffffffu, l2);
                if (r != INF_I) { m_match = base + r; break; }
            }
        }
    } else {
        // Overflow (never on this data): exact chunked early-exit full scan.
        for (int base = 0; base < M_PAD; base += 128) {
            const float4 v0 = bp[base + lane];
            const float4 v1 = bp[base + 32 + lane];
            const float4 v2 = bp[base + 64 + lane];
            const float4 v3 = bp[base + 96 + lane];
            int l2 = INF_I;
            if (iou_hit(v3, A.x, A.y, A.z, A.w, s1)) l2 = 96 + lane;
            if (iou_hit(v2, A.x, A.y, A.z, A.w, s1)) l2 = 64 + lane;
            if (iou_hit(v1, A.x, A.y, A.z, A.w, s1)) l2 = 32 + lane;
            if (iou_hit(v0, A.x, A.y, A.z, A.w, s1)) l2 = lane;
            const int r = __reduce_min_sync(0xffffffffu, l2);
            if (r != INF_I) { m_match = base + r; break; }
        }
    }

    if (lane == 0) s_m[k] = m_match;

    if (m_match >= 0) {
        // Cooperative entropy of the matched row: C=80 = 32 + 32 + 16.
        const float* __restrict__ row =
            conf + ((size_t)k * M_BOX + (size_t)m_match) * C_CLS;
        float s;
        {
            const float p0 = row[lane];
            const float p1 = row[lane + 32];
            s = p0 * __logf(p0) + p1 * __logf(p1);
        }
        if (lane < C_CLS - 64) {
            const float p2 = row[lane + 64];
            s += p2 * __logf(p2);
        }
        #pragma unroll
        for (int off = 16; off; off >>= 1)
            s += __shfl_xor_sync(0xffffffffu, s, off);
        // u = 1 - entropy/log(C) = 1 + s/log(C)
        if (lane == 0) s_u[k] = 1.0f + s * (1.0f / logf((float)C_CLS));
    }

    __syncthreads();

    if (tid == 0) {
        float sum = 0.0f;
        int   cc = 0;
        #pragma unroll
        for (int kk = 0; kk < K_PASS; kk++) {
            if (s_m[kk] >= 0) { sum += s_u[kk]; cc++; }
        }
        out[n] = (cc > 0) ? (sum / (float)cc) : __int_as_float(0x7fc00000);
    }
}

extern "C" void kernel_launch(void* const* d_in, const int* in_sizes, int n_in,
                              void* d_out, int out_size)
{
    const float* pred = (const float*)d_in[0];
    const float* dp   = (const float*)d_in[1];
    const float* conf = (const float*)d_in[2];
    float* out = (float*)d_out;

    prep_kernel<<<(K_PASS * M_PAD + 255) / 256, 256>>>(pred, dp);
    ue_cls_kernel<<<N_PRED, K_PASS * 32>>>(conf, out);
}

// round 8
// speedup vs baseline: 1.1637x; 1.0833x over previous
#include <cuda_runtime.h>
#include <math.h>

// Shapes fixed by the reference:
//   pred:              [N, 6]
//   dropout_preds:     [K, M, 6]
//   dropout_cls_confs: [K, M, C]
//   out:               [N]
#define N_PRED 1000
#define M_BOX  2000
#define K_PASS 10
#define C_CLS  80
#define EPS_F  1e-7f
#define CAP    32
#define INF_I  0x7fffffff

// Max |jittered copy - source pred|_inf over all K*N copies (float bits).
// atomicMax only ever raises it to the same data-determined value -> replay-safe.
__device__ unsigned g_dev = 0;

__global__ void prep_kernel(const float* __restrict__ pred,
                            const float* __restrict__ dp)
{
    const int i = blockIdx.x * blockDim.x + threadIdx.x;   // over K*N copies
    float dev = 0.0f;
    if (i < K_PASS * N_PRED) {
        const int kk = i / N_PRED;
        const int mm = i - kk * N_PRED;
        const float* b = dp + ((size_t)kk * M_BOX + mm) * 6;
        const float* p = pred + (size_t)mm * 6;
        dev = fmaxf(fmaxf(fabsf(b[0] - p[0]), fabsf(b[1] - p[1])),
                    fmaxf(fabsf(b[2] - p[2]), fabsf(b[3] - p[3])));
    }
    __shared__ unsigned s_w[8];
    const unsigned wmax = __reduce_max_sync(0xffffffffu, __float_as_uint(dev));
    if ((threadIdx.x & 31) == 0) s_w[threadIdx.x >> 5] = wmax;
    __syncthreads();
    if (threadIdx.x == 0) {
        unsigned m = 0;
        #pragma unroll
        for (int w = 0; w < (int)(blockDim.x >> 5); w++) m = max(m, s_w[w]);
        atomicMax(&g_dev, m);
    }
}

// Exact: IoU > 0.5  <=>  3*inter > (area1+eps) + area2   (s1 = area1+eps)
__device__ __forceinline__ bool hit_box(const float* __restrict__ b,
                                        float ax1, float ay1, float ax2, float ay2,
                                        float s1)
{
    const float2 b01 = *reinterpret_cast<const float2*>(b);
    const float2 b23 = *reinterpret_cast<const float2*>(b + 2);
    const float w = fminf(ax2, b23.x) - fmaxf(ax1, b01.x);
    const float h = fminf(ay2, b23.y) - fmaxf(ay1, b01.y);
    const float inter = fmaxf(w, 0.0f) * fmaxf(h, 0.0f);
    const float area2 = (b23.x - b01.x) * (b23.y - b01.y);
    return fmaf(3.0f, inter, -area2) > s1;
}

// Exact chunked early-exit scan of dp rows [start, M_BOX); returns first match or -1.
__device__ __forceinline__ int scan_range(const float* __restrict__ dpk, int start,
                                          float ax1, float ay1, float ax2, float ay2,
                                          float s1, int lane)
{
    for (int base = start; base < M_BOX; base += 128) {
        int l2 = INF_I;
        #pragma unroll
        for (int j = 3; j >= 0; j--) {
            const int m = base + j * 32 + lane;
            if (m < M_BOX && hit_box(dpk + (size_t)m * 6, ax1, ay1, ax2, ay2, s1))
                l2 = j * 32 + lane;            // j descending -> min kept naturally
        }
        const int r = __reduce_min_sync(0xffffffffu, l2);
        if (r != INF_I) return base + r;
    }
    return -1;
}

// One block per pred n; one warp per pass k.
// Phase 0: speculative prefetch of conf row (k, n) -- m_match == n almost always.
// Phase 1: screen all preds with a SOUND IoU upper bound (jitter <= D).
// Phase 2: exact test of candidates; min hit index == first match (< any random idx).
__global__ __launch_bounds__(K_PASS * 32)
void ue_cls_kernel(const float* __restrict__ pred,
                   const float* __restrict__ dp,
                   const float* __restrict__ conf,
                   float* __restrict__ out)
{
    const int n    = blockIdx.x;
    const int tid  = threadIdx.x;
    const int k    = tid >> 5;
    const int lane = tid & 31;

    __shared__ int   s_cand[CAP];
    __shared__ int   s_cnt;
    __shared__ float s_u[K_PASS];
    __shared__ int   s_m[K_PASS];

    // ---- Phase 0: speculative conf prefetch (overlaps everything below) ----
    const float* __restrict__ rs = conf + ((size_t)k * M_BOX + n) * C_CLS;
    float q0 = rs[lane];
    float q1 = rs[lane + 32];
    float q2 = (lane < C_CLS - 64) ? rs[lane + 64] : 1.0f;   // log(1)=0 -> no-op lanes

    // Pred box A
    const float2 a01 = *reinterpret_cast<const float2*>(pred + (size_t)n * 6);
    const float2 a23 = *reinterpret_cast<const float2*>(pred + (size_t)n * 6 + 2);
    const float ax1 = a01.x, ay1 = a01.y, ax2 = a23.x, ay2 = a23.y;
    const float a1 = (ax2 - ax1) * (ay2 - ay1);
    const float s1 = a1 + EPS_F;
    const float Dv = __uint_as_float(g_dev) * 1.01f + 0.5f;  // inflated: sound

    if (tid == 0) s_cnt = 0;
    __syncthreads();

    // ---- Phase 1: sound candidate screen over all preds (~3 per thread) ----
    for (int n2 = tid; n2 < N_PRED; n2 += K_PASS * 32) {
        const float2 b01 = *reinterpret_cast<const float2*>(pred + (size_t)n2 * 6);
        const float2 b23 = *reinterpret_cast<const float2*>(pred + (size_t)n2 * 6 + 2);
        const float w_ub = fminf(ax2, b23.x + Dv) - fmaxf(ax1, b01.x - Dv);
        const float h_ub = fminf(ay2, b23.y + Dv) - fmaxf(ay1, b01.y - Dv);
        const float inter_ub = fmaxf(w_ub, 0.0f) * fmaxf(h_ub, 0.0f);
        const float a2_lb = fmaxf(b23.x - b01.x - 2.0f * Dv, 0.0f) *
                            fmaxf(b23.y - b01.y - 2.0f * Dv, 0.0f);
        if (3.0f * inter_ub > a1 + a2_lb) {
            const int pos = atomicAdd(&s_cnt, 1);
            if (pos < CAP) s_cand[pos] = n2;
        }
    }
    __syncthreads();
    const int cnt = s_cnt;

    const float* __restrict__ dpk = dp + (size_t)k * M_BOX * 6;
    int m_match;

    if (cnt <= CAP) {
        // ---- Phase 2: exact test of candidate copies (indices < 1000) ----
        int loc = INF_I;
        for (int c = lane; c < cnt; c += 32) {
            const int m = s_cand[c];
            if (hit_box(dpk + (size_t)m * 6, ax1, ay1, ax2, ay2, s1))
                loc = min(loc, m);
        }
        m_match = __reduce_min_sync(0xffffffffu, loc);
        if (m_match == INF_I)   // no copy hit: first match (if any) is random region
            m_match = scan_range(dpk, N_PRED, ax1, ay1, ax2, ay2, s1, lane);
    } else {
        // Overflow (never on this data): exact full scan.
        m_match = scan_range(dpk, 0, ax1, ay1, ax2, ay2, s1, lane);
    }

    if (lane == 0) s_m[k] = m_match;

    if (m_match >= 0) {
        if (m_match != n) {   // rare mispredict: reload the true row
            const float* __restrict__ row =
                conf + ((size_t)k * M_BOX + (size_t)m_match) * C_CLS;
            q0 = row[lane];
            q1 = row[lane + 32];
            q2 = (lane < C_CLS - 64) ? row[lane + 64] : 1.0f;
        }
        float s = q0 * __logf(q0) + q1 * __logf(q1) + q2 * __logf(q2);
        #pragma unroll
        for (int off = 16; off; off >>= 1)
            s += __shfl_xor_sync(0xffffffffu, s, off);
        // u = 1 - entropy/log(C) = 1 + s/log(C)
        if (lane == 0) s_u[k] = 1.0f + s * (1.0f / logf((float)C_CLS));
    }

    __syncthreads();

    if (tid == 0) {
        float sum = 0.0f;
        int   cc = 0;
        #pragma unroll
        for (int kk = 0; kk < K_PASS; kk++) {
            if (s_m[kk] >= 0) { sum += s_u[kk]; cc++; }
        }
        out[n] = (cc > 0) ? (sum / (float)cc) : __int_as_float(0x7fc00000);
    }
}

extern "C" void kernel_launch(void* const* d_in, const int* in_sizes, int n_in,
                              void* d_out, int out_size)
{
    const float* pred = (const float*)d_in[0];
    const float* dp   = (const float*)d_in[1];
    const float* conf = (const float*)d_in[2];
    float* out = (float*)d_out;

    prep_kernel<<<(K_PASS * N_PRED + 255) / 256, 256>>>(pred, dp);
    ue_cls_kernel<<<N_PRED, K_PASS * 32>>>(pred, dp, conf, out);
}